// round 2
// baseline (speedup 1.0000x reference)
#include <cuda_runtime.h>
#include <math.h>

// Problem constants (fixed-shape problem)
#define NB   4
#define LQ   2048
#define SK   2048
#define NH   8
#define DH   64
#define BM   64      // query rows per CTA
#define BS   64      // kv rows per tile
#define NTHR 256
#define TSTRIDE 68   // padded stride for transposed [d][row] tiles and P tile

// Dynamic smem layout (floats):
//   Qs [DH][TSTRIDE]  transposed Q tile
//   Ks [DH][TSTRIDE]  transposed K tile
//   Vs [BS][DH]       natural V tile
//   Ps [BM][TSTRIDE]  probabilities tile
//   kbias[BS], qbias[BM]
#define SMEM_FLOATS (2*DH*TSTRIDE + BS*DH + BM*TSTRIDE + BS + BM)
#define SMEM_BYTES  (SMEM_FLOATS * 4)

__global__ __launch_bounds__(NTHR)
void fullattn_kernel(const float* __restrict__ Q, const float* __restrict__ K,
                     const float* __restrict__ V,
                     const int* __restrict__ qmask,
                     const int* __restrict__ kvmask,
                     float* __restrict__ O)
{
    extern __shared__ float sm[];
    float* Qs    = sm;                       // [DH][TSTRIDE]
    float* Ks    = Qs + DH*TSTRIDE;          // [DH][TSTRIDE]
    float* Vs    = Ks + DH*TSTRIDE;          // [BS][DH]
    float* Ps    = Vs + BS*DH;               // [BM][TSTRIDE]
    float* kbias = Ps + BM*TSTRIDE;          // [BS]
    float* qbias = kbias + BS;               // [BM]

    const int tid  = threadIdx.x;
    const int tx   = tid & 15;               // column group (16)
    const int ty   = tid >> 4;               // row group (16)
    const int row0 = ty * 4;
    const int col0 = tx * 4;

    const int ltile = blockIdx.x;
    const int h     = blockIdx.y;
    const int n     = blockIdx.z;
    const int l0    = ltile * BM;
    const int rowstride = NH * DH;           // 512 floats between consecutive seq positions

    const float* Qg = Q + ((size_t)n*LQ + l0) * rowstride + h*DH;
    const float* Kg = K + (size_t)n*SK * rowstride + h*DH;
    const float* Vg = V + (size_t)n*SK * rowstride + h*DH;
    float*       Og = O + ((size_t)n*LQ + l0) * rowstride + h*DH;

    // ---- Load Q tile transposed: thread mapping d-major so STS is conflict-free ----
    #pragma unroll
    for (int i = 0; i < 4; i++) {
        int idx = tid + i*NTHR;              // 0..1023 quads
        int r  = idx & 63;                   // query row within tile
        int dv = idx >> 6;                   // d-vector (float4) index
        float4 v = *(const float4*)(Qg + (size_t)r*rowstride + dv*4);
        Qs[(dv*4+0)*TSTRIDE + r] = v.x;
        Qs[(dv*4+1)*TSTRIDE + r] = v.y;
        Qs[(dv*4+2)*TSTRIDE + r] = v.z;
        Qs[(dv*4+3)*TSTRIDE + r] = v.w;
    }
    if (tid < BM)
        qbias[tid] = (qmask[(size_t)n*LQ + l0 + tid] != 0) ? 0.0f : -INFINITY;

    float acc[4][4];
    float mrow[4], lrow[4];
    #pragma unroll
    for (int r = 0; r < 4; r++) {
        mrow[r] = -INFINITY;
        lrow[r] = 0.0f;
        #pragma unroll
        for (int c = 0; c < 4; c++) acc[r][c] = 0.0f;
    }

    for (int s0 = 0; s0 < SK; s0 += BS) {
        __syncthreads();   // previous tile's smem reads complete; safe to overwrite

        int myv = 0;
        if (tid < BS) {
            int mv = kvmask[(size_t)n*SK + s0 + tid];
            kbias[tid] = (mv != 0) ? 0.0f : -INFINITY;
            myv = (mv != 0);
        }
        // Fully-masked tile contributes exactly zero (all p = exp(-inf)=0): skip
        // before even touching K/V in global memory.
        if (!__syncthreads_or(myv)) continue;

        // ---- Load K tile transposed ----
        #pragma unroll
        for (int i = 0; i < 4; i++) {
            int idx = tid + i*NTHR;
            int r  = idx & 63;
            int dv = idx >> 6;
            float4 v = *(const float4*)(Kg + (size_t)(s0 + r)*rowstride + dv*4);
            Ks[(dv*4+0)*TSTRIDE + r] = v.x;
            Ks[(dv*4+1)*TSTRIDE + r] = v.y;
            Ks[(dv*4+2)*TSTRIDE + r] = v.z;
            Ks[(dv*4+3)*TSTRIDE + r] = v.w;
        }
        // ---- Load V tile natural [s][d] (fully coalesced, conflict-free) ----
        #pragma unroll
        for (int i = 0; i < 4; i++) {
            int idx = tid + i*NTHR;
            int r  = idx >> 4;
            int dv = idx & 15;
            float4 v = *(const float4*)(Vg + (size_t)(s0 + r)*rowstride + dv*4);
            *(float4*)(Vs + r*DH + dv*4) = v;
        }
        __syncthreads();   // tiles + kbias visible

        // ---- GEMM1: S = Q @ K^T (4x4 microtile per thread) ----
        float sv[4][4];
        #pragma unroll
        for (int r = 0; r < 4; r++)
            #pragma unroll
            for (int c = 0; c < 4; c++) sv[r][c] = 0.0f;

        #pragma unroll 8
        for (int d = 0; d < DH; d++) {
            float4 a4 = *(const float4*)(Qs + d*TSTRIDE + row0);
            float4 b4 = *(const float4*)(Ks + d*TSTRIDE + col0);
            float av[4] = {a4.x, a4.y, a4.z, a4.w};
            float bv[4] = {b4.x, b4.y, b4.z, b4.w};
            #pragma unroll
            for (int r = 0; r < 4; r++)
                #pragma unroll
                for (int c = 0; c < 4; c++)
                    sv[r][c] += av[r] * bv[c];
        }

        float kb[4], qb[4];
        #pragma unroll
        for (int c = 0; c < 4; c++) kb[c] = kbias[col0 + c];
        #pragma unroll
        for (int r = 0; r < 4; r++) qb[r] = qbias[row0 + r];

        // ---- Online softmax (row groups of 16 lanes: xor-shuffles stay in-group) ----
        #pragma unroll
        for (int r = 0; r < 4; r++) {
            float rm = -INFINITY;
            #pragma unroll
            for (int c = 0; c < 4; c++) {
                sv[r][c] = sv[r][c] * 0.125f + kb[c] + qb[r];   // 0.125 = 1/sqrt(64)
                rm = fmaxf(rm, sv[r][c]);
            }
            #pragma unroll
            for (int o = 1; o < 16; o <<= 1)
                rm = fmaxf(rm, __shfl_xor_sync(0xffffffffu, rm, o));

            float mnew  = fmaxf(mrow[r], rm);
            float scale = __expf(mrow[r] - mnew);   // exp(-inf)=0 on first valid tile

            float psum = 0.0f;
            #pragma unroll
            for (int c = 0; c < 4; c++) {
                float p = __expf(sv[r][c] - mnew);  // masked cols: exp(-inf)=0
                sv[r][c] = p;
                psum += p;
            }
            #pragma unroll
            for (int o = 1; o < 16; o <<= 1)
                psum += __shfl_xor_sync(0xffffffffu, psum, o);

            lrow[r] = lrow[r] * scale + psum;
            mrow[r] = mnew;
            #pragma unroll
            for (int c = 0; c < 4; c++) acc[r][c] *= scale;

            *(float4*)(Ps + (row0 + r)*TSTRIDE + col0) =
                make_float4(sv[r][0], sv[r][1], sv[r][2], sv[r][3]);
        }
        __syncthreads();   // P tile visible

        // ---- GEMM2: O += P @ V ----
        #pragma unroll 8
        for (int s = 0; s < BS; s++) {
            float4 b4 = *(const float4*)(Vs + s*DH + col0);
            float bv[4] = {b4.x, b4.y, b4.z, b4.w};
            #pragma unroll
            for (int r = 0; r < 4; r++) {
                float a = Ps[(row0 + r)*TSTRIDE + s];  // broadcast across tx group
                #pragma unroll
                for (int c = 0; c < 4; c++)
                    acc[r][c] += a * bv[c];
            }
        }
    }

    // ---- Epilogue: normalize and store ----
    #pragma unroll
    for (int r = 0; r < 4; r++) {
        float inv = 1.0f / lrow[r];
        float4 o;
        o.x = acc[r][0] * inv;
        o.y = acc[r][1] * inv;
        o.z = acc[r][2] * inv;
        o.w = acc[r][3] * inv;
        *(float4*)(Og + (size_t)(row0 + r)*rowstride + col0) = o;
    }
}

extern "C" void kernel_launch(void* const* d_in, const int* in_sizes, int n_in,
                              void* d_out, int out_size)
{
    const float* Q   = (const float*)d_in[0];
    const float* K   = (const float*)d_in[1];
    const float* V   = (const float*)d_in[2];
    const int*   qm  = (const int*)d_in[3];
    const int*   kvm = (const int*)d_in[4];
    float*       O   = (float*)d_out;

    (void)in_sizes; (void)n_in; (void)out_size;

    cudaFuncSetAttribute(fullattn_kernel,
                         cudaFuncAttributeMaxDynamicSharedMemorySize, SMEM_BYTES);

    dim3 grid(LQ / BM, NH, NB);
    fullattn_kernel<<<grid, NTHR, SMEM_BYTES>>>(Q, K, V, qm, kvm, O);
}

// round 3
// speedup vs baseline: 1.0734x; 1.0734x over previous
#include <cuda_runtime.h>
#include <math.h>

// Problem constants
#define NB   4
#define LQ   2048
#define SK   2048
#define NH   8
#define DH   64
#define BM   128     // query rows per CTA
#define BS   64      // kv rows per tile
#define NTHR 256
#define BMP  132     // padded stride for Qs transposed [d][row]
#define BSP  68      // padded stride for Ks transposed and Ps rows

// smem layout (floats):
//   Qs [DH][BMP]   transposed Q tile     8448
//   Ks [DH][BSP]   transposed K tile     4352
//   Vs [BS][DH]    natural V tile        4096
//   Ps [BM][BSP]   probabilities         8704
//   kbias[BS], qbias[BM]                  192
#define SMEM_FLOATS (DH*BMP + DH*BSP + BS*DH + BM*BSP + BS + BM)
#define SMEM_BYTES  (SMEM_FLOATS * 4)

__global__ __launch_bounds__(NTHR, 2)
void fullattn_kernel(const float* __restrict__ Q, const float* __restrict__ K,
                     const float* __restrict__ V,
                     const int* __restrict__ qmask,
                     const int* __restrict__ kvmask,
                     float* __restrict__ O)
{
    extern __shared__ float sm[];
    float* Qs    = sm;                        // [DH][BMP]
    float* Ks    = Qs + DH*BMP;               // [DH][BSP]
    float* Vs    = Ks + DH*BSP;               // [BS][DH]
    float* Ps    = Vs + BS*DH;                // [BM][BSP]
    float* kbias = Ps + BM*BSP;               // [BS]
    float* qbias = kbias + BS;                // [BM]

    const int tid  = threadIdx.x;
    const int tx   = tid & 15;                // 16 column groups (4 cols each)
    const int ty   = tid >> 4;                // 16 row groups (8 rows each)
    const int row0 = ty * 8;
    const int col0 = tx * 4;

    const int l0 = blockIdx.x * BM;
    const int h  = blockIdx.y;
    const int n  = blockIdx.z;
    const int rowstride = NH * DH;            // 512 floats

    const float* Qg = Q + ((size_t)n*LQ + l0) * rowstride + h*DH;
    const float* Kg = K + (size_t)n*SK * rowstride + h*DH;
    const float* Vg = V + (size_t)n*SK * rowstride + h*DH;
    float*       Og = O + ((size_t)n*LQ + l0) * rowstride + h*DH;

    // ---- Load Q tile transposed: [d][row], conflict-free scalar STS ----
    #pragma unroll
    for (int i = 0; i < 8; i++) {
        int idx = tid + i*NTHR;               // 0..2047 float4 quads
        int r  = idx & 127;                   // query row
        int dv = idx >> 7;                    // d-vector index
        float4 v = *(const float4*)(Qg + (size_t)r*rowstride + dv*4);
        Qs[(dv*4+0)*BMP + r] = v.x;
        Qs[(dv*4+1)*BMP + r] = v.y;
        Qs[(dv*4+2)*BMP + r] = v.z;
        Qs[(dv*4+3)*BMP + r] = v.w;
    }
    if (tid < BM)
        qbias[tid] = (qmask[(size_t)n*LQ + l0 + tid] != 0) ? 0.0f : -INFINITY;
    __syncthreads();

    // Hoist qbias for my 8 rows into registers
    float qb[8];
    #pragma unroll
    for (int r = 0; r < 8; r++) qb[r] = qbias[row0 + r];

    float acc[8][4];
    float mrow[8], lrow[8];
    #pragma unroll
    for (int r = 0; r < 8; r++) {
        mrow[r] = -INFINITY;
        lrow[r] = 0.0f;
        #pragma unroll
        for (int c = 0; c < 4; c++) acc[r][c] = 0.0f;
    }

    for (int s0 = 0; s0 < SK; s0 += BS) {
        __syncthreads();   // previous tile's smem reads complete

        int myv = 0;
        if (tid < BS) {
            int mv = kvmask[(size_t)n*SK + s0 + tid];
            kbias[tid] = (mv != 0) ? 0.0f : -INFINITY;
            myv = (mv != 0);
        }
        // Fully-masked tile contributes exactly zero: skip before loading K/V.
        if (!__syncthreads_or(myv)) continue;

        // ---- Load K tile transposed [d][s] ----
        #pragma unroll
        for (int i = 0; i < 4; i++) {
            int idx = tid + i*NTHR;           // 0..1023 quads
            int r  = idx & 63;
            int dv = idx >> 6;
            float4 v = *(const float4*)(Kg + (size_t)(s0 + r)*rowstride + dv*4);
            Ks[(dv*4+0)*BSP + r] = v.x;
            Ks[(dv*4+1)*BSP + r] = v.y;
            Ks[(dv*4+2)*BSP + r] = v.z;
            Ks[(dv*4+3)*BSP + r] = v.w;
        }
        // ---- Load V tile natural [s][d] ----
        #pragma unroll
        for (int i = 0; i < 4; i++) {
            int idx = tid + i*NTHR;
            int r  = idx >> 4;
            int dv = idx & 15;
            float4 v = *(const float4*)(Vg + (size_t)(s0 + r)*rowstride + dv*4);
            *(float4*)(Vs + r*DH + dv*4) = v;
        }
        __syncthreads();   // tiles + kbias visible

        // ---- GEMM1: S = Q @ K^T  (8x4 microtile; A-loads broadcast in tx group) ----
        float sv[8][4];
        #pragma unroll
        for (int r = 0; r < 8; r++)
            #pragma unroll
            for (int c = 0; c < 4; c++) sv[r][c] = 0.0f;

        #pragma unroll 8
        for (int d = 0; d < DH; d++) {
            float4 a0 = *(const float4*)(Qs + d*BMP + row0);
            float4 a1 = *(const float4*)(Qs + d*BMP + row0 + 4);
            float4 b4 = *(const float4*)(Ks + d*BSP + col0);
            float av[8] = {a0.x, a0.y, a0.z, a0.w, a1.x, a1.y, a1.z, a1.w};
            float bv[4] = {b4.x, b4.y, b4.z, b4.w};
            #pragma unroll
            for (int r = 0; r < 8; r++)
                #pragma unroll
                for (int c = 0; c < 4; c++)
                    sv[r][c] += av[r] * bv[c];
        }

        float kb[4];
        #pragma unroll
        for (int c = 0; c < 4; c++) kb[c] = kbias[col0 + c];

        // ---- Online softmax (16-lane xor-shuffle reductions within tx group) ----
        #pragma unroll
        for (int r = 0; r < 8; r++) {
            float rm = -INFINITY;
            #pragma unroll
            for (int c = 0; c < 4; c++) {
                sv[r][c] = sv[r][c] * 0.125f + kb[c] + qb[r];   // 0.125 = 1/sqrt(64)
                rm = fmaxf(rm, sv[r][c]);
            }
            #pragma unroll
            for (int o = 1; o < 16; o <<= 1)
                rm = fmaxf(rm, __shfl_xor_sync(0xffffffffu, rm, o));

            float mnew  = fmaxf(mrow[r], rm);
            float scale = __expf(mrow[r] - mnew);

            float psum = 0.0f;
            #pragma unroll
            for (int c = 0; c < 4; c++) {
                float p = __expf(sv[r][c] - mnew);
                sv[r][c] = p;
                psum += p;
            }
            #pragma unroll
            for (int o = 1; o < 16; o <<= 1)
                psum += __shfl_xor_sync(0xffffffffu, psum, o);

            lrow[r] = lrow[r] * scale + psum;
            mrow[r] = mnew;
            #pragma unroll
            for (int c = 0; c < 4; c++) acc[r][c] *= scale;

            *(float4*)(Ps + (row0 + r)*BSP + col0) =
                make_float4(sv[r][0], sv[r][1], sv[r][2], sv[r][3]);
        }
        __syncthreads();   // P tile visible

        // ---- GEMM2: O += P @ V  (P rows cached 4 s-cols at a time; broadcast) ----
        #pragma unroll 2
        for (int sb = 0; sb < BS; sb += 4) {
            float4 p4[8];
            #pragma unroll
            for (int r = 0; r < 8; r++)
                p4[r] = *(const float4*)(Ps + (row0 + r)*BSP + sb);
            #pragma unroll
            for (int j = 0; j < 4; j++) {
                float4 b4 = *(const float4*)(Vs + (sb + j)*DH + col0);
                float bv[4] = {b4.x, b4.y, b4.z, b4.w};
                float pj[8] = {p4[0].x, p4[1].x, p4[2].x, p4[3].x,
                               p4[4].x, p4[5].x, p4[6].x, p4[7].x};
                if (j == 1) { pj[0]=p4[0].y; pj[1]=p4[1].y; pj[2]=p4[2].y; pj[3]=p4[3].y;
                              pj[4]=p4[4].y; pj[5]=p4[5].y; pj[6]=p4[6].y; pj[7]=p4[7].y; }
                if (j == 2) { pj[0]=p4[0].z; pj[1]=p4[1].z; pj[2]=p4[2].z; pj[3]=p4[3].z;
                              pj[4]=p4[4].z; pj[5]=p4[5].z; pj[6]=p4[6].z; pj[7]=p4[7].z; }
                if (j == 3) { pj[0]=p4[0].w; pj[1]=p4[1].w; pj[2]=p4[2].w; pj[3]=p4[3].w;
                              pj[4]=p4[4].w; pj[5]=p4[5].w; pj[6]=p4[6].w; pj[7]=p4[7].w; }
                #pragma unroll
                for (int r = 0; r < 8; r++)
                    #pragma unroll
                    for (int c = 0; c < 4; c++)
                        acc[r][c] += pj[r] * bv[c];
            }
        }
    }

    // ---- Epilogue: normalize and store ----
    #pragma unroll
    for (int r = 0; r < 8; r++) {
        float inv = 1.0f / lrow[r];
        float4 o;
        o.x = acc[r][0] * inv;
        o.y = acc[r][1] * inv;
        o.z = acc[r][2] * inv;
        o.w = acc[r][3] * inv;
        *(float4*)(Og + (size_t)(row0 + r)*rowstride + col0) = o;
    }
}

extern "C" void kernel_launch(void* const* d_in, const int* in_sizes, int n_in,
                              void* d_out, int out_size)
{
    const float* Q   = (const float*)d_in[0];
    const float* K   = (const float*)d_in[1];
    const float* V   = (const float*)d_in[2];
    const int*   qm  = (const int*)d_in[3];
    const int*   kvm = (const int*)d_in[4];
    float*       O   = (float*)d_out;

    (void)in_sizes; (void)n_in; (void)out_size;

    cudaFuncSetAttribute(fullattn_kernel,
                         cudaFuncAttributeMaxDynamicSharedMemorySize, SMEM_BYTES);

    dim3 grid(LQ / BM, NH, NB);
    fullattn_kernel<<<grid, NTHR, SMEM_BYTES>>>(Q, K, V, qm, kvm, O);
}

// round 4
// speedup vs baseline: 1.2757x; 1.1884x over previous
#include <cuda_runtime.h>
#include <math.h>
#include <stdint.h>

// Problem constants
#define NB   4
#define LQ   2048
#define SK   2048
#define NH   8
#define DH   64
#define BM   128     // query rows per CTA
#define BS   64      // kv tile
#define NTHR 256     // 8 warps; warp w owns rows [16w, 16w+16)
#define KSP  68      // padded row stride (floats) for K/V tiles
#define PSP  68      // padded row stride for P tile

// smem (floats): Ks[64][68] natural, Vs[64][68] transposed [d][s],
//                Ps[128][68], kbias[64]
#define SMEM_FLOATS (BS*KSP + DH*KSP + BM*PSP + BS)
#define SMEM_BYTES  (SMEM_FLOATS * 4)

// m16n8k8 tf32 mma, accumulate in place
__device__ __forceinline__ void mma8(float* c,
                                     uint32_t a0, uint32_t a1, uint32_t a2, uint32_t a3,
                                     uint32_t b0, uint32_t b1)
{
    asm volatile(
        "mma.sync.aligned.m16n8k8.row.col.f32.tf32.tf32.f32 "
        "{%0,%1,%2,%3}, {%4,%5,%6,%7}, {%8,%9}, {%0,%1,%2,%3};\n"
        : "+f"(c[0]), "+f"(c[1]), "+f"(c[2]), "+f"(c[3])
        : "r"(a0), "r"(a1), "r"(a2), "r"(a3), "r"(b0), "r"(b1));
}

// tf32 low-part: x - truncate_to_tf32(x)  (hw truncates mma operands to tf32)
__device__ __forceinline__ uint32_t lo_part(float x) {
    float hi = __int_as_float(__float_as_int(x) & 0xFFFFE000);
    return __float_as_uint(x - hi);
}

// FFMA-only exp (no MUFU): exp(x) = 2^(x*log2e); magic-round + deg-6 Taylor.
// Clamp handles -inf and NaN (fmaxf returns the non-NaN operand).
__device__ __forceinline__ float fexp(float x) {
    x = fmaxf(x, -87.0f);
    float t  = x * 1.4426950408889634f;
    float z  = t + 12582912.0f;              // 1.5*2^23: round(t) in mantissa
    float fi = z - 12582912.0f;
    float f  = t - fi;                       // f in [-0.5, 0.5]
    float q;
    q = fmaf(1.5403530393381609e-4f, f, 1.3333558146428443e-3f);
    q = fmaf(q, f, 9.6181291076284771e-3f);
    q = fmaf(q, f, 5.5504108664821580e-2f);
    q = fmaf(q, f, 2.4022650695910072e-1f);
    q = fmaf(q, f, 6.9314718055994531e-1f);
    q = fmaf(q, f, 1.0f);
    int e = (__float_as_int(z) - 0x4B400000 + 127) << 23;   // 2^round(t)
    return q * __int_as_float(e);
}

__global__ __launch_bounds__(NTHR, 1)
void fullattn_mma(const float* __restrict__ Q, const float* __restrict__ K,
                  const float* __restrict__ V,
                  const int* __restrict__ qmask,
                  const int* __restrict__ kvmask,
                  float* __restrict__ O)
{
    extern __shared__ float sm[];
    float* Ks    = sm;                 // [BS][KSP]  natural [s][d]
    float* Vs    = Ks + BS*KSP;        // [DH][KSP]  transposed [d][s]
    float* Ps    = Vs + DH*KSP;        // [BM][PSP]
    float* kbias = Ps + BM*PSP;        // [BS]

    const int tid  = threadIdx.x;
    const int wid  = tid >> 5;
    const int lane = tid & 31;
    const int lq   = lane >> 2;        // 0..7  (fragment row/col group)
    const int lr   = lane & 3;         // 0..3

    const int l0 = blockIdx.x * BM;
    const int h  = blockIdx.y;
    const int n  = blockIdx.z;
    const int RS = NH * DH;            // 512 floats between seq positions

    const int rowA = wid*16 + lq;      // my two output rows within tile
    const int rowB = rowA + 8;

    const float* Kg = K + (size_t)n*SK*RS + h*DH;
    const float* Vg = V + (size_t)n*SK*RS + h*DH;
    const float* QA = Q + ((size_t)n*LQ + l0 + rowA)*RS + h*DH;
    const float* QB = Q + ((size_t)n*LQ + l0 + rowB)*RS + h*DH;

    // ---- Q fragments (persistent in regs): raw (acts as tf32-hi) + lo ----
    uint32_t qr[8][4], ql[8][4];
    #pragma unroll
    for (int kt = 0; kt < 8; kt++) {
        float a0 = QA[kt*8 + lr];
        float a1 = QB[kt*8 + lr];
        float a2 = QA[kt*8 + lr + 4];
        float a3 = QB[kt*8 + lr + 4];
        qr[kt][0] = __float_as_uint(a0); ql[kt][0] = lo_part(a0);
        qr[kt][1] = __float_as_uint(a1); ql[kt][1] = lo_part(a1);
        qr[kt][2] = __float_as_uint(a2); ql[kt][2] = lo_part(a2);
        qr[kt][3] = __float_as_uint(a3); ql[kt][3] = lo_part(a3);
    }
    const float qbA = (qmask[(size_t)n*LQ + l0 + rowA] != 0) ? 0.0f : -INFINITY;
    const float qbB = (qmask[(size_t)n*LQ + l0 + rowB] != 0) ? 0.0f : -INFINITY;

    float Oacc[8][4];
    #pragma unroll
    for (int nt = 0; nt < 8; nt++)
        #pragma unroll
        for (int j = 0; j < 4; j++) Oacc[nt][j] = 0.0f;
    float mA = -INFINITY, mB = -INFINITY, lA = 0.0f, lB = 0.0f;

    for (int s0 = 0; s0 < SK; s0 += BS) {
        __syncthreads();   // all warps done reading Ks/Vs/Ps of previous tile

        int myv = 0;
        if (tid < BS) {
            int mv = kvmask[(size_t)n*SK + s0 + tid];
            kbias[tid] = (mv != 0) ? 0.0f : -INFINITY;
            myv = (mv != 0);
        }
        if (!__syncthreads_or(myv)) continue;   // fully-masked tile: skip

        // ---- stage K natural [s][d] ----
        #pragma unroll
        for (int i = 0; i < 4; i++) {
            int idx = tid + i*NTHR;            // 1024 float4s
            int s  = idx >> 4;
            int dv = idx & 15;
            float4 v = *(const float4*)(Kg + (size_t)(s0 + s)*RS + dv*4);
            *(float4*)(Ks + s*KSP + dv*4) = v;
        }
        // ---- stage V transposed [d][s] ----
        #pragma unroll
        for (int i = 0; i < 4; i++) {
            int idx = tid + i*NTHR;
            int s  = idx & 63;
            int dv = idx >> 6;
            float4 v = *(const float4*)(Vg + (size_t)(s0 + s)*RS + dv*4);
            Vs[(dv*4+0)*KSP + s] = v.x;
            Vs[(dv*4+1)*KSP + s] = v.y;
            Vs[(dv*4+2)*KSP + s] = v.z;
            Vs[(dv*4+3)*KSP + s] = v.w;
        }
        __syncthreads();

        // ---- GEMM1: S = Q @ K^T  (3xTF32) ----
        float Sacc[8][4];
        #pragma unroll
        for (int nt = 0; nt < 8; nt++)
            #pragma unroll
            for (int j = 0; j < 4; j++) Sacc[nt][j] = 0.0f;

        #pragma unroll
        for (int kt = 0; kt < 8; kt++) {
            #pragma unroll
            for (int nt = 0; nt < 8; nt++) {
                float b0 = Ks[(nt*8 + lq)*KSP + kt*8 + lr];
                float b1 = Ks[(nt*8 + lq)*KSP + kt*8 + lr + 4];
                uint32_t b0r = __float_as_uint(b0), b1r = __float_as_uint(b1);
                uint32_t b0l = lo_part(b0),        b1l = lo_part(b1);
                mma8(Sacc[nt], qr[kt][0], qr[kt][1], qr[kt][2], qr[kt][3], b0r, b1r);
                mma8(Sacc[nt], qr[kt][0], qr[kt][1], qr[kt][2], qr[kt][3], b0l, b1l);
                mma8(Sacc[nt], ql[kt][0], ql[kt][1], ql[kt][2], ql[kt][3], b0r, b1r);
            }
        }

        // ---- softmax on C fragments (rows rowA, rowB; 4 lanes per row) ----
        float rmA = -INFINITY, rmB = -INFINITY;
        #pragma unroll
        for (int nt = 0; nt < 8; nt++) {
            float2 kb = *(const float2*)&kbias[nt*8 + 2*lr];
            Sacc[nt][0] = fmaf(Sacc[nt][0], 0.125f, kb.x + qbA);
            Sacc[nt][1] = fmaf(Sacc[nt][1], 0.125f, kb.y + qbA);
            Sacc[nt][2] = fmaf(Sacc[nt][2], 0.125f, kb.x + qbB);
            Sacc[nt][3] = fmaf(Sacc[nt][3], 0.125f, kb.y + qbB);
            rmA = fmaxf(rmA, fmaxf(Sacc[nt][0], Sacc[nt][1]));
            rmB = fmaxf(rmB, fmaxf(Sacc[nt][2], Sacc[nt][3]));
        }
        rmA = fmaxf(rmA, __shfl_xor_sync(0xffffffffu, rmA, 1));
        rmA = fmaxf(rmA, __shfl_xor_sync(0xffffffffu, rmA, 2));
        rmB = fmaxf(rmB, __shfl_xor_sync(0xffffffffu, rmB, 1));
        rmB = fmaxf(rmB, __shfl_xor_sync(0xffffffffu, rmB, 2));

        float mnA = fmaxf(mA, rmA), mnB = fmaxf(mB, rmB);
        float scA = fexp(mA - mnA), scB = fexp(mB - mnB);
        mA = mnA; mB = mnB;

        float psA = 0.0f, psB = 0.0f;
        #pragma unroll
        for (int nt = 0; nt < 8; nt++) {
            float p0 = fexp(Sacc[nt][0] - mnA);
            float p1 = fexp(Sacc[nt][1] - mnA);
            float p2 = fexp(Sacc[nt][2] - mnB);
            float p3 = fexp(Sacc[nt][3] - mnB);
            psA += p0 + p1;  psB += p2 + p3;
            *(float2*)&Ps[rowA*PSP + nt*8 + 2*lr] = make_float2(p0, p1);
            *(float2*)&Ps[rowB*PSP + nt*8 + 2*lr] = make_float2(p2, p3);
            #pragma unroll
            for (int j = 0; j < 2; j++) { Oacc[nt][j]   *= scA; Oacc[nt][j+2] *= scB; }
        }
        psA += __shfl_xor_sync(0xffffffffu, psA, 1);
        psA += __shfl_xor_sync(0xffffffffu, psA, 2);
        psB += __shfl_xor_sync(0xffffffffu, psB, 1);
        psB += __shfl_xor_sync(0xffffffffu, psB, 2);
        lA = lA*scA + psA;
        lB = lB*scB + psB;
        __syncthreads();   // Ps visible to all warps

        // ---- GEMM2: O += P @ V  (3xTF32; A=P from smem, B=V transposed) ----
        #pragma unroll
        for (int kt = 0; kt < 8; kt++) {
            float a0 = Ps[rowA*PSP + kt*8 + lr];
            float a1 = Ps[rowB*PSP + kt*8 + lr];
            float a2 = Ps[rowA*PSP + kt*8 + lr + 4];
            float a3 = Ps[rowB*PSP + kt*8 + lr + 4];
            uint32_t a0r = __float_as_uint(a0), a1r = __float_as_uint(a1);
            uint32_t a2r = __float_as_uint(a2), a3r = __float_as_uint(a3);
            uint32_t a0l = lo_part(a0), a1l = lo_part(a1);
            uint32_t a2l = lo_part(a2), a3l = lo_part(a3);
            #pragma unroll
            for (int nt = 0; nt < 8; nt++) {
                float b0 = Vs[(nt*8 + lq)*KSP + kt*8 + lr];
                float b1 = Vs[(nt*8 + lq)*KSP + kt*8 + lr + 4];
                uint32_t b0r = __float_as_uint(b0), b1r = __float_as_uint(b1);
                uint32_t b0l = lo_part(b0),        b1l = lo_part(b1);
                mma8(Oacc[nt], a0r, a1r, a2r, a3r, b0r, b1r);
                mma8(Oacc[nt], a0r, a1r, a2r, a3r, b0l, b1l);
                mma8(Oacc[nt], a0l, a1l, a2l, a3l, b0r, b1r);
            }
        }
    }

    // ---- epilogue ----
    float invA = 1.0f / lA, invB = 1.0f / lB;
    float* OA = O + ((size_t)n*LQ + l0 + rowA)*RS + h*DH;
    float* OB = O + ((size_t)n*LQ + l0 + rowB)*RS + h*DH;
    #pragma unroll
    for (int nt = 0; nt < 8; nt++) {
        *(float2*)(OA + nt*8 + 2*lr) = make_float2(Oacc[nt][0]*invA, Oacc[nt][1]*invA);
        *(float2*)(OB + nt*8 + 2*lr) = make_float2(Oacc[nt][2]*invB, Oacc[nt][3]*invB);
    }
}

extern "C" void kernel_launch(void* const* d_in, const int* in_sizes, int n_in,
                              void* d_out, int out_size)
{
    const float* Q   = (const float*)d_in[0];
    const float* K   = (const float*)d_in[1];
    const float* V   = (const float*)d_in[2];
    const int*   qm  = (const int*)d_in[3];
    const int*   kvm = (const int*)d_in[4];
    float*       O   = (float*)d_out;

    (void)in_sizes; (void)n_in; (void)out_size;

    cudaFuncSetAttribute(fullattn_mma,
                         cudaFuncAttributeMaxDynamicSharedMemorySize, SMEM_BYTES);

    dim3 grid(LQ / BM, NH, NB);
    fullattn_mma<<<grid, NTHR, SMEM_BYTES>>>(Q, K, V, qm, kvm, O);
}

// round 5
// speedup vs baseline: 1.3380x; 1.0489x over previous
#include <cuda_runtime.h>
#include <math.h>
#include <stdint.h>

// Problem constants
#define NB   4
#define LQ   2048
#define SK   2048
#define NH   8
#define DH   64
#define BM   128     // query rows per CTA
#define BS   64      // kv tile
#define NTHR 256     // 8 warps
#define NTILES (SK/BS)
#define KSP  68      // padded row stride for K/V tiles (conflict-free B loads)
#define PSP  68      // padded row stride for P tile

// smem layout (floats)
#define OFF_KR   0                       // Kr[2][BS*KSP] raw K, double-buffered
#define OFF_VR   (2*BS*KSP)              // Vr[2][BS*KSP]
#define OFF_KLO  (4*BS*KSP)              // Klo[BS*KSP]
#define OFF_VLO  (OFF_KLO + BS*KSP)      // Vlo[BS*KSP]
#define OFF_PS   (OFF_VLO + BS*KSP)      // Ps[BM*PSP]
#define OFF_KB   (OFF_PS + BM*PSP)       // kbias[BS]
#define SMEM_FLOATS (OFF_KB + BS)
#define SMEM_BYTES  (SMEM_FLOATS * 4)

// m16n8k8 tf32 mma, accumulate in place
__device__ __forceinline__ void mma8(float* c,
                                     uint32_t a0, uint32_t a1, uint32_t a2, uint32_t a3,
                                     uint32_t b0, uint32_t b1)
{
    asm volatile(
        "mma.sync.aligned.m16n8k8.row.col.f32.tf32.tf32.f32 "
        "{%0,%1,%2,%3}, {%4,%5,%6,%7}, {%8,%9}, {%0,%1,%2,%3};\n"
        : "+f"(c[0]), "+f"(c[1]), "+f"(c[2]), "+f"(c[3])
        : "r"(a0), "r"(a1), "r"(a2), "r"(a3), "r"(b0), "r"(b1));
}

__device__ __forceinline__ float lo_f(float x) {
    float hi = __int_as_float(__float_as_int(x) & 0xFFFFE000);
    return x - hi;
}
__device__ __forceinline__ uint32_t lo_part(float x) { return __float_as_uint(lo_f(x)); }

// FFMA-only exp (no MUFU)
__device__ __forceinline__ float fexp(float x) {
    x = fmaxf(x, -87.0f);
    float t  = x * 1.4426950408889634f;
    float z  = t + 12582912.0f;
    float fi = z - 12582912.0f;
    float f  = t - fi;
    float q;
    q = fmaf(1.5403530393381609e-4f, f, 1.3333558146428443e-3f);
    q = fmaf(q, f, 9.6181291076284771e-3f);
    q = fmaf(q, f, 5.5504108664821580e-2f);
    q = fmaf(q, f, 2.4022650695910072e-1f);
    q = fmaf(q, f, 6.9314718055994531e-1f);
    q = fmaf(q, f, 1.0f);
    int e = (__float_as_int(z) - 0x4B400000 + 127) << 23;
    return q * __int_as_float(e);
}

__device__ __forceinline__ void cpasync16(uint32_t dst, const float* src) {
    asm volatile("cp.async.cg.shared.global [%0], [%1], 16;" :: "r"(dst), "l"(src));
}

__global__ __launch_bounds__(NTHR, 1)
void fullattn_mma(const float* __restrict__ Q, const float* __restrict__ K,
                  const float* __restrict__ V,
                  const int* __restrict__ qmask,
                  const int* __restrict__ kvmask,
                  float* __restrict__ O)
{
    extern __shared__ float sm[];
    float* Kr    = sm + OFF_KR;
    float* Vr    = sm + OFF_VR;
    float* Klo   = sm + OFF_KLO;
    float* Vlo   = sm + OFF_VLO;
    float* Ps    = sm + OFF_PS;
    float* kbias = sm + OFF_KB;
    __shared__ int tval[NTILES];
    __shared__ int vlist[NTILES];
    __shared__ int nvalid_s;

    const int tid  = threadIdx.x;
    const int wid  = tid >> 5;
    const int lane = tid & 31;
    const int lq   = lane >> 2;
    const int lr   = lane & 3;

    const int l0 = blockIdx.x * BM;
    const int h  = blockIdx.y;
    const int n  = blockIdx.z;
    const int RS = NH * DH;            // 512

    const int rowA = wid*16 + lq;
    const int rowB = rowA + 8;

    const float* Kg = K + (size_t)n*SK*RS + h*DH;
    const float* Vg = V + (size_t)n*SK*RS + h*DH;
    const float* QA = Q + ((size_t)n*LQ + l0 + rowA)*RS + h*DH;
    const float* QB = Q + ((size_t)n*LQ + l0 + rowB)*RS + h*DH;

    // ---- tile validity (warp-parallel ballot) ----
    for (int j = wid; j < NTILES; j += 8) {
        int m0 = kvmask[(size_t)n*SK + j*BS + lane*2];
        int m1 = kvmask[(size_t)n*SK + j*BS + lane*2 + 1];
        unsigned b = __ballot_sync(0xffffffffu, (m0 | m1) != 0);
        if (lane == 0) tval[j] = (b != 0);
    }

    // ---- Q fragments persistent in regs: raw(hi) + lo ----
    uint32_t qr[8][4], ql[8][4];
    #pragma unroll
    for (int kt = 0; kt < 8; kt++) {
        float a0 = QA[kt*8 + lr];
        float a1 = QB[kt*8 + lr];
        float a2 = QA[kt*8 + lr + 4];
        float a3 = QB[kt*8 + lr + 4];
        qr[kt][0] = __float_as_uint(a0); ql[kt][0] = lo_part(a0);
        qr[kt][1] = __float_as_uint(a1); ql[kt][1] = lo_part(a1);
        qr[kt][2] = __float_as_uint(a2); ql[kt][2] = lo_part(a2);
        qr[kt][3] = __float_as_uint(a3); ql[kt][3] = lo_part(a3);
    }
    const float qbA = (qmask[(size_t)n*LQ + l0 + rowA] != 0) ? 0.0f : -INFINITY;
    const float qbB = (qmask[(size_t)n*LQ + l0 + rowB] != 0) ? 0.0f : -INFINITY;

    __syncthreads();
    if (tid == 0) {
        int c = 0;
        for (int j = 0; j < NTILES; j++) if (tval[j]) vlist[c++] = j;
        nvalid_s = c;
    }
    __syncthreads();
    const int nv = nvalid_s;

    // chunk mapping for cp.async staging (4 16B chunks each for K and V)
    int cs[4], cc[4];
    #pragma unroll
    for (int i = 0; i < 4; i++) {
        int idx = tid + i*NTHR;        // 0..1023
        cs[i] = idx >> 4;              // row s (0..63)
        cc[i] = (idx & 15) * 4;        // float col (0,4,...,60)
    }

    // ---- prologue: stage first valid tile into buffer 0 ----
    if (nv > 0) {
        int t0 = vlist[0];
        #pragma unroll
        for (int i = 0; i < 4; i++) {
            uint32_t dk = (uint32_t)__cvta_generic_to_shared(Kr + cs[i]*KSP + cc[i]);
            uint32_t dv = (uint32_t)__cvta_generic_to_shared(Vr + cs[i]*KSP + cc[i]);
            cpasync16(dk, Kg + (size_t)(t0*BS + cs[i])*RS + cc[i]);
            cpasync16(dv, Vg + (size_t)(t0*BS + cs[i])*RS + cc[i]);
        }
        asm volatile("cp.async.commit_group;" ::: "memory");
        asm volatile("cp.async.wait_group 0;" ::: "memory");
    }
    __syncthreads();

    float Oacc[8][4];
    #pragma unroll
    for (int nt = 0; nt < 8; nt++)
        #pragma unroll
        for (int j = 0; j < 4; j++) Oacc[nt][j] = 0.0f;
    float mA = -INFINITY, mB = -INFINITY, lA = 0.0f, lB = 0.0f;

    int buf = 0;
    for (int it = 0; it < nv; it++) {
        const int t = vlist[it];
        float* Krb = Kr + buf*BS*KSP;
        float* Vrb = Vr + buf*BS*KSP;

        // ---- prefetch next valid tile into the other buffer ----
        if (it + 1 < nv) {
            int tn = vlist[it+1];
            float* Krd = Kr + (buf^1)*BS*KSP;
            float* Vrd = Vr + (buf^1)*BS*KSP;
            #pragma unroll
            for (int i = 0; i < 4; i++) {
                uint32_t dk = (uint32_t)__cvta_generic_to_shared(Krd + cs[i]*KSP + cc[i]);
                uint32_t dv = (uint32_t)__cvta_generic_to_shared(Vrd + cs[i]*KSP + cc[i]);
                cpasync16(dk, Kg + (size_t)(tn*BS + cs[i])*RS + cc[i]);
                cpasync16(dv, Vg + (size_t)(tn*BS + cs[i])*RS + cc[i]);
            }
        }
        asm volatile("cp.async.commit_group;" ::: "memory");

        // ---- repack: compute lo arrays once per CTA (phase-conflict-free) ----
        {
            int s  = tid & 63;
            int dq = (tid >> 6) * 16;
            #pragma unroll
            for (int j = 0; j < 4; j++) {
                float4 k4 = *(const float4*)(Krb + s*KSP + dq + j*4);
                float4 v4 = *(const float4*)(Vrb + s*KSP + dq + j*4);
                float4 kl, vl;
                kl.x = lo_f(k4.x); kl.y = lo_f(k4.y); kl.z = lo_f(k4.z); kl.w = lo_f(k4.w);
                vl.x = lo_f(v4.x); vl.y = lo_f(v4.y); vl.z = lo_f(v4.z); vl.w = lo_f(v4.w);
                *(float4*)(Klo + s*KSP + dq + j*4) = kl;
                *(float4*)(Vlo + s*KSP + dq + j*4) = vl;
            }
        }
        if (tid < BS)
            kbias[tid] = (kvmask[(size_t)n*SK + t*BS + tid] != 0) ? 0.0f : -INFINITY;
        __syncthreads();

        // ---- GEMM1: S = Q @ K^T (3xTF32; pure LDS+MMA inner loop) ----
        float Sacc[8][4];
        #pragma unroll
        for (int nt = 0; nt < 8; nt++)
            #pragma unroll
            for (int j = 0; j < 4; j++) Sacc[nt][j] = 0.0f;

        #pragma unroll
        for (int kt = 0; kt < 8; kt++) {
            #pragma unroll
            for (int nt = 0; nt < 8; nt++) {
                int bidx = (nt*8 + lq)*KSP + kt*8 + lr;
                uint32_t b0r = __float_as_uint(Krb[bidx]);
                uint32_t b1r = __float_as_uint(Krb[bidx + 4]);
                uint32_t b0l = __float_as_uint(Klo[bidx]);
                uint32_t b1l = __float_as_uint(Klo[bidx + 4]);
                mma8(Sacc[nt], qr[kt][0], qr[kt][1], qr[kt][2], qr[kt][3], b0r, b1r);
                mma8(Sacc[nt], qr[kt][0], qr[kt][1], qr[kt][2], qr[kt][3], b0l, b1l);
                mma8(Sacc[nt], ql[kt][0], ql[kt][1], ql[kt][2], ql[kt][3], b0r, b1r);
            }
        }

        // ---- online softmax ----
        float rmA = -INFINITY, rmB = -INFINITY;
        #pragma unroll
        for (int nt = 0; nt < 8; nt++) {
            float2 kb = *(const float2*)&kbias[nt*8 + 2*lr];
            Sacc[nt][0] = fmaf(Sacc[nt][0], 0.125f, kb.x + qbA);
            Sacc[nt][1] = fmaf(Sacc[nt][1], 0.125f, kb.y + qbA);
            Sacc[nt][2] = fmaf(Sacc[nt][2], 0.125f, kb.x + qbB);
            Sacc[nt][3] = fmaf(Sacc[nt][3], 0.125f, kb.y + qbB);
            rmA = fmaxf(rmA, fmaxf(Sacc[nt][0], Sacc[nt][1]));
            rmB = fmaxf(rmB, fmaxf(Sacc[nt][2], Sacc[nt][3]));
        }
        rmA = fmaxf(rmA, __shfl_xor_sync(0xffffffffu, rmA, 1));
        rmA = fmaxf(rmA, __shfl_xor_sync(0xffffffffu, rmA, 2));
        rmB = fmaxf(rmB, __shfl_xor_sync(0xffffffffu, rmB, 1));
        rmB = fmaxf(rmB, __shfl_xor_sync(0xffffffffu, rmB, 2));

        float mnA = fmaxf(mA, rmA), mnB = fmaxf(mB, rmB);
        float scA = fexp(mA - mnA), scB = fexp(mB - mnB);
        mA = mnA; mB = mnB;

        float psA = 0.0f, psB = 0.0f;
        #pragma unroll
        for (int nt = 0; nt < 8; nt++) {
            float p0 = fexp(Sacc[nt][0] - mnA);
            float p1 = fexp(Sacc[nt][1] - mnA);
            float p2 = fexp(Sacc[nt][2] - mnB);
            float p3 = fexp(Sacc[nt][3] - mnB);
            psA += p0 + p1;  psB += p2 + p3;
            *(float2*)&Ps[rowA*PSP + nt*8 + 2*lr] = make_float2(p0, p1);
            *(float2*)&Ps[rowB*PSP + nt*8 + 2*lr] = make_float2(p2, p3);
            #pragma unroll
            for (int j = 0; j < 2; j++) { Oacc[nt][j] *= scA; Oacc[nt][j+2] *= scB; }
        }
        psA += __shfl_xor_sync(0xffffffffu, psA, 1);
        psA += __shfl_xor_sync(0xffffffffu, psA, 2);
        psB += __shfl_xor_sync(0xffffffffu, psB, 1);
        psB += __shfl_xor_sync(0xffffffffu, psB, 2);
        lA = lA*scA + psA;
        lB = lB*scB + psB;
        __syncthreads();   // Ps visible; GEMM1 reads of Krb/Klo complete

        // ---- GEMM2: O += P @ V (2xTF32: trunc-P x (V_hi + V_lo)) ----
        #pragma unroll
        for (int kt = 0; kt < 8; kt++) {
            uint32_t a0 = __float_as_uint(Ps[rowA*PSP + kt*8 + lr]);
            uint32_t a1 = __float_as_uint(Ps[rowB*PSP + kt*8 + lr]);
            uint32_t a2 = __float_as_uint(Ps[rowA*PSP + kt*8 + lr + 4]);
            uint32_t a3 = __float_as_uint(Ps[rowB*PSP + kt*8 + lr + 4]);
            #pragma unroll
            for (int nt = 0; nt < 8; nt++) {
                int b0i = (kt*8 + lr)*KSP + nt*8 + lq;
                int b1i = (kt*8 + lr + 4)*KSP + nt*8 + lq;
                uint32_t b0r = __float_as_uint(Vrb[b0i]);
                uint32_t b1r = __float_as_uint(Vrb[b1i]);
                uint32_t b0l = __float_as_uint(Vlo[b0i]);
                uint32_t b1l = __float_as_uint(Vlo[b1i]);
                mma8(Oacc[nt], a0, a1, a2, a3, b0r, b1r);
                mma8(Oacc[nt], a0, a1, a2, a3, b0l, b1l);
            }
        }

        asm volatile("cp.async.wait_group 0;" ::: "memory");  // next tile staged
        __syncthreads();
        buf ^= 1;
    }

    // ---- epilogue ----
    float invA = 1.0f / lA, invB = 1.0f / lB;
    float* OA = O + ((size_t)n*LQ + l0 + rowA)*RS + h*DH;
    float* OB = O + ((size_t)n*LQ + l0 + rowB)*RS + h*DH;
    #pragma unroll
    for (int nt = 0; nt < 8; nt++) {
        *(float2*)(OA + nt*8 + 2*lr) = make_float2(Oacc[nt][0]*invA, Oacc[nt][1]*invA);
        *(float2*)(OB + nt*8 + 2*lr) = make_float2(Oacc[nt][2]*invB, Oacc[nt][3]*invB);
    }
}

extern "C" void kernel_launch(void* const* d_in, const int* in_sizes, int n_in,
                              void* d_out, int out_size)
{
    const float* Q   = (const float*)d_in[0];
    const float* K   = (const float*)d_in[1];
    const float* V   = (const float*)d_in[2];
    const int*   qm  = (const int*)d_in[3];
    const int*   kvm = (const int*)d_in[4];
    float*       O   = (float*)d_out;

    (void)in_sizes; (void)n_in; (void)out_size;

    cudaFuncSetAttribute(fullattn_mma,
                         cudaFuncAttributeMaxDynamicSharedMemorySize, SMEM_BYTES);

    dim3 grid(LQ / BM, NH, NB);
    fullattn_mma<<<grid, NTHR, SMEM_BYTES>>>(Q, K, V, qm, kvm, O);
}

// round 6
// speedup vs baseline: 2.1464x; 1.6041x over previous
#include <cuda_runtime.h>
#include <math.h>
#include <stdint.h>

// Problem constants
#define NB   4
#define LQ   2048
#define SK   2048
#define NH   8
#define DH   64
#define BM   128     // query rows per CTA
#define BS   64      // kv tile
#define NTHR 256     // 8 warps
#define NTILES (SK/BS)
#define KSP  68      // raw staging row stride (floats)
#define KHS  36      // Kh/Kl row stride (u32 pairs), conflict-free B loads
#define VTS  37      // Vth/Vtl row stride (u32 pairs), conflict-free B loads

// smem layout (in floats/u32 words)
#define OFF_KR   0                        // Kr[BS*KSP] raw K (fp32)
#define OFF_VR   (OFF_KR + BS*KSP)        // Vr[BS*KSP] raw V
#define OFF_KH   (OFF_VR + BS*KSP)        // Kh[BS*KHS] bf16x2 hi
#define OFF_KL   (OFF_KH + BS*KHS)        // Kl[BS*KHS] bf16x2 lo
#define OFF_VTH  (OFF_KL + BS*KHS)        // Vth[DH*VTS] transposed bf16x2 hi
#define OFF_VTL  (OFF_VTH + DH*VTS)       // Vtl[DH*VTS]
#define OFF_KB   (OFF_VTL + DH*VTS)       // kbias[BS]
#define SMEM_WORDS (OFF_KB + BS)
#define SMEM_BYTES (SMEM_WORDS * 4)

// m16n8k16 bf16 mma, accumulate in place
__device__ __forceinline__ void mma16(float* c,
                                      uint32_t a0, uint32_t a1, uint32_t a2, uint32_t a3,
                                      uint32_t b0, uint32_t b1)
{
    asm volatile(
        "mma.sync.aligned.m16n8k16.row.col.f32.bf16.bf16.f32 "
        "{%0,%1,%2,%3}, {%4,%5,%6,%7}, {%8,%9}, {%0,%1,%2,%3};\n"
        : "+f"(c[0]), "+f"(c[1]), "+f"(c[2]), "+f"(c[3])
        : "r"(a0), "r"(a1), "r"(a2), "r"(a3), "r"(b0), "r"(b1));
}

// pack (x0 -> low half, x1 -> high half) as bf16x2 (rn)
__device__ __forceinline__ uint32_t bfpair(float x0, float x1) {
    uint32_t r;
    asm("cvt.rn.bf16x2.f32 %0, %1, %2;" : "=r"(r) : "f"(x1), "f"(x0));
    return r;
}
// residual pair: (x0,x1) minus the bf16 values stored in h
__device__ __forceinline__ uint32_t bfres(uint32_t h, float x0, float x1) {
    float h0 = __uint_as_float(h << 16);
    float h1 = __uint_as_float(h & 0xFFFF0000u);
    return bfpair(x0 - h0, x1 - h1);
}

// FFMA-only exp (no MUFU)
__device__ __forceinline__ float fexp(float x) {
    x = fmaxf(x, -87.0f);
    float t  = x * 1.4426950408889634f;
    float z  = t + 12582912.0f;
    float fi = z - 12582912.0f;
    float f  = t - fi;
    float q;
    q = fmaf(1.5403530393381609e-4f, f, 1.3333558146428443e-3f);
    q = fmaf(q, f, 9.6181291076284771e-3f);
    q = fmaf(q, f, 5.5504108664821580e-2f);
    q = fmaf(q, f, 2.4022650695910072e-1f);
    q = fmaf(q, f, 6.9314718055994531e-1f);
    q = fmaf(q, f, 1.0f);
    int e = (__float_as_int(z) - 0x4B400000 + 127) << 23;
    return q * __int_as_float(e);
}

__device__ __forceinline__ void cpasync16(uint32_t dst, const float* src) {
    asm volatile("cp.async.cg.shared.global [%0], [%1], 16;" :: "r"(dst), "l"(src));
}

__global__ __launch_bounds__(NTHR, 2)
void fullattn_bf16(const float* __restrict__ Q, const float* __restrict__ K,
                   const float* __restrict__ V,
                   const int* __restrict__ qmask,
                   const int* __restrict__ kvmask,
                   float* __restrict__ O)
{
    extern __shared__ float sm[];
    float*    Kr    = sm + OFF_KR;
    float*    Vr    = sm + OFF_VR;
    uint32_t* Kh    = (uint32_t*)(sm + OFF_KH);
    uint32_t* Kl    = (uint32_t*)(sm + OFF_KL);
    uint32_t* Vth   = (uint32_t*)(sm + OFF_VTH);
    uint32_t* Vtl   = (uint32_t*)(sm + OFF_VTL);
    float*    kbias = sm + OFF_KB;
    __shared__ int tval[NTILES];
    __shared__ int vlist[NTILES];
    __shared__ int nvalid_s;

    const int tid  = threadIdx.x;
    const int wid  = tid >> 5;
    const int lane = tid & 31;
    const int lq   = lane >> 2;
    const int lr   = lane & 3;

    const int l0 = blockIdx.x * BM;
    const int h  = blockIdx.y;
    const int n  = blockIdx.z;
    const int RS = NH * DH;            // 512

    const int rowA = wid*16 + lq;
    const int rowB = rowA + 8;

    const float* Kg = K + (size_t)n*SK*RS + h*DH;
    const float* Vg = V + (size_t)n*SK*RS + h*DH;
    const float* QA = Q + ((size_t)n*LQ + l0 + rowA)*RS + h*DH;
    const float* QB = Q + ((size_t)n*LQ + l0 + rowB)*RS + h*DH;

    // ---- tile validity (warp-parallel ballot) ----
    for (int j = wid; j < NTILES; j += 8) {
        int m0 = kvmask[(size_t)n*SK + j*BS + lane*2];
        int m1 = kvmask[(size_t)n*SK + j*BS + lane*2 + 1];
        unsigned b = __ballot_sync(0xffffffffu, (m0 | m1) != 0);
        if (lane == 0) tval[j] = (b != 0);
    }

    // ---- Q fragments persistent in regs as bf16 hi+lo (m16n8k16 A layout) ----
    uint32_t qh[4][4], ql[4][4];
    #pragma unroll
    for (int kc = 0; kc < 4; kc++) {
        float x0 = QA[kc*16 + 2*lr],     x1 = QA[kc*16 + 2*lr + 1];
        float y0 = QB[kc*16 + 2*lr],     y1 = QB[kc*16 + 2*lr + 1];
        float z0 = QA[kc*16 + 2*lr + 8], z1 = QA[kc*16 + 2*lr + 9];
        float w0 = QB[kc*16 + 2*lr + 8], w1 = QB[kc*16 + 2*lr + 9];
        qh[kc][0] = bfpair(x0, x1); ql[kc][0] = bfres(qh[kc][0], x0, x1);
        qh[kc][1] = bfpair(y0, y1); ql[kc][1] = bfres(qh[kc][1], y0, y1);
        qh[kc][2] = bfpair(z0, z1); ql[kc][2] = bfres(qh[kc][2], z0, z1);
        qh[kc][3] = bfpair(w0, w1); ql[kc][3] = bfres(qh[kc][3], w0, w1);
    }
    const float qbA = (qmask[(size_t)n*LQ + l0 + rowA] != 0) ? 0.0f : -INFINITY;
    const float qbB = (qmask[(size_t)n*LQ + l0 + rowB] != 0) ? 0.0f : -INFINITY;

    __syncthreads();
    if (tid == 0) {
        int c = 0;
        for (int j = 0; j < NTILES; j++) if (tval[j]) vlist[c++] = j;
        nvalid_s = c;
    }
    __syncthreads();
    const int nv = nvalid_s;

    // cp.async chunk mapping (4 chunks of 16B each for K and V)
    int cs[4], cc[4];
    #pragma unroll
    for (int i = 0; i < 4; i++) {
        int idx = tid + i*NTHR;
        cs[i] = idx >> 4;
        cc[i] = (idx & 15) * 4;
    }

    // ---- prologue: stage first valid tile into raw buffers ----
    if (nv > 0) {
        int t0 = vlist[0];
        #pragma unroll
        for (int i = 0; i < 4; i++) {
            uint32_t dk = (uint32_t)__cvta_generic_to_shared(Kr + cs[i]*KSP + cc[i]);
            uint32_t dv = (uint32_t)__cvta_generic_to_shared(Vr + cs[i]*KSP + cc[i]);
            cpasync16(dk, Kg + (size_t)(t0*BS + cs[i])*RS + cc[i]);
            cpasync16(dv, Vg + (size_t)(t0*BS + cs[i])*RS + cc[i]);
        }
        asm volatile("cp.async.commit_group;" ::: "memory");
    }

    float Oacc[8][4];
    #pragma unroll
    for (int nt = 0; nt < 8; nt++)
        #pragma unroll
        for (int j = 0; j < 4; j++) Oacc[nt][j] = 0.0f;
    float mA = -INFINITY, mB = -INFINITY, lA = 0.0f, lB = 0.0f;

    for (int it = 0; it < nv; it++) {
        const int t = vlist[it];

        asm volatile("cp.async.wait_group 0;" ::: "memory");   // raw = tile it
        __syncthreads();

        // ---- convert raw fp32 -> packed bf16x2 hi/lo ----
        {   // K: [s][d] -> Kh/Kl [s][dpair], stride KHS
            int s  = tid >> 2;
            int p0 = (tid & 3) * 8;
            #pragma unroll
            for (int j = 0; j < 8; j++) {
                int p = p0 + j;
                float2 x = *(const float2*)(Kr + s*KSP + p*2);
                uint32_t hh = bfpair(x.x, x.y);
                Kh[s*KHS + p] = hh;
                Kl[s*KHS + p] = bfres(hh, x.x, x.y);
            }
        }
        {   // V: [s][d] -> transposed Vth/Vtl [d][spair], stride VTS
            int d  = tid & 63;
            int j0 = (tid >> 6) * 8;
            #pragma unroll
            for (int j = 0; j < 8; j++) {
                int sp = j0 + j;
                float v0 = Vr[(2*sp)*KSP + d];
                float v1 = Vr[(2*sp+1)*KSP + d];
                uint32_t hh = bfpair(v0, v1);
                Vth[d*VTS + sp] = hh;
                Vtl[d*VTS + sp] = bfres(hh, v0, v1);
            }
        }
        if (tid < BS)
            kbias[tid] = (kvmask[(size_t)n*SK + t*BS + tid] != 0) ? 0.0f : -INFINITY;
        __syncthreads();   // bf16 tiles + kbias ready; raw buffers free

        // ---- prefetch next valid tile into raw (overlaps compute below) ----
        if (it + 1 < nv) {
            int tn = vlist[it+1];
            #pragma unroll
            for (int i = 0; i < 4; i++) {
                uint32_t dk = (uint32_t)__cvta_generic_to_shared(Kr + cs[i]*KSP + cc[i]);
                uint32_t dv = (uint32_t)__cvta_generic_to_shared(Vr + cs[i]*KSP + cc[i]);
                cpasync16(dk, Kg + (size_t)(tn*BS + cs[i])*RS + cc[i]);
                cpasync16(dv, Vg + (size_t)(tn*BS + cs[i])*RS + cc[i]);
            }
        }
        asm volatile("cp.async.commit_group;" ::: "memory");

        // ---- GEMM1: S = Q @ K^T  (3x bf16 split) ----
        float Sacc[8][4];
        #pragma unroll
        for (int nt = 0; nt < 8; nt++)
            #pragma unroll
            for (int j = 0; j < 4; j++) Sacc[nt][j] = 0.0f;

        #pragma unroll
        for (int kc = 0; kc < 4; kc++) {
            #pragma unroll
            for (int nt = 0; nt < 8; nt++) {
                int bi = (nt*8 + lq)*KHS + kc*8 + lr;
                uint32_t b0h = Kh[bi], b1h = Kh[bi + 4];
                uint32_t b0l = Kl[bi], b1l = Kl[bi + 4];
                mma16(Sacc[nt], qh[kc][0], qh[kc][1], qh[kc][2], qh[kc][3], b0h, b1h);
                mma16(Sacc[nt], qh[kc][0], qh[kc][1], qh[kc][2], qh[kc][3], b0l, b1l);
                mma16(Sacc[nt], ql[kc][0], ql[kc][1], ql[kc][2], ql[kc][3], b0h, b1h);
            }
        }

        // ---- online softmax (in registers) ----
        float rmA = -INFINITY, rmB = -INFINITY;
        #pragma unroll
        for (int nt = 0; nt < 8; nt++) {
            float2 kb = *(const float2*)&kbias[nt*8 + 2*lr];
            Sacc[nt][0] = fmaf(Sacc[nt][0], 0.125f, kb.x + qbA);
            Sacc[nt][1] = fmaf(Sacc[nt][1], 0.125f, kb.y + qbA);
            Sacc[nt][2] = fmaf(Sacc[nt][2], 0.125f, kb.x + qbB);
            Sacc[nt][3] = fmaf(Sacc[nt][3], 0.125f, kb.y + qbB);
            rmA = fmaxf(rmA, fmaxf(Sacc[nt][0], Sacc[nt][1]));
            rmB = fmaxf(rmB, fmaxf(Sacc[nt][2], Sacc[nt][3]));
        }
        rmA = fmaxf(rmA, __shfl_xor_sync(0xffffffffu, rmA, 1));
        rmA = fmaxf(rmA, __shfl_xor_sync(0xffffffffu, rmA, 2));
        rmB = fmaxf(rmB, __shfl_xor_sync(0xffffffffu, rmB, 1));
        rmB = fmaxf(rmB, __shfl_xor_sync(0xffffffffu, rmB, 2));

        float mnA = fmaxf(mA, rmA), mnB = fmaxf(mB, rmB);
        float scA = fexp(mA - mnA), scB = fexp(mB - mnB);
        mA = mnA; mB = mnB;

        float psA = 0.0f, psB = 0.0f;
        #pragma unroll
        for (int nt = 0; nt < 8; nt++) {
            float p0 = fexp(Sacc[nt][0] - mnA);
            float p1 = fexp(Sacc[nt][1] - mnA);
            float p2 = fexp(Sacc[nt][2] - mnB);
            float p3 = fexp(Sacc[nt][3] - mnB);
            psA += p0 + p1;  psB += p2 + p3;
            Sacc[nt][0] = p0; Sacc[nt][1] = p1; Sacc[nt][2] = p2; Sacc[nt][3] = p3;
            #pragma unroll
            for (int j = 0; j < 2; j++) { Oacc[nt][j] *= scA; Oacc[nt][j+2] *= scB; }
        }
        psA += __shfl_xor_sync(0xffffffffu, psA, 1);
        psA += __shfl_xor_sync(0xffffffffu, psA, 2);
        psB += __shfl_xor_sync(0xffffffffu, psB, 1);
        psB += __shfl_xor_sync(0xffffffffu, psB, 2);
        lA = lA*scA + psA;
        lB = lB*scB + psB;

        // ---- GEMM2: O += P @ V  (P frags built in registers; 3x bf16 split) ----
        #pragma unroll
        for (int kc = 0; kc < 4; kc++) {
            // A-fragment of P for k-chunk kc straight from Sacc (C-layout == A-layout)
            uint32_t a0h = bfpair(Sacc[2*kc][0],   Sacc[2*kc][1]);
            uint32_t a1h = bfpair(Sacc[2*kc][2],   Sacc[2*kc][3]);
            uint32_t a2h = bfpair(Sacc[2*kc+1][0], Sacc[2*kc+1][1]);
            uint32_t a3h = bfpair(Sacc[2*kc+1][2], Sacc[2*kc+1][3]);
            uint32_t a0l = bfres(a0h, Sacc[2*kc][0],   Sacc[2*kc][1]);
            uint32_t a1l = bfres(a1h, Sacc[2*kc][2],   Sacc[2*kc][3]);
            uint32_t a2l = bfres(a2h, Sacc[2*kc+1][0], Sacc[2*kc+1][1]);
            uint32_t a3l = bfres(a3h, Sacc[2*kc+1][2], Sacc[2*kc+1][3]);
            #pragma unroll
            for (int nt = 0; nt < 8; nt++) {
                int bi = (nt*8 + lq)*VTS + kc*8 + lr;
                uint32_t b0h = Vth[bi], b1h = Vth[bi + 4];
                uint32_t b0l = Vtl[bi], b1l = Vtl[bi + 4];
                mma16(Oacc[nt], a0h, a1h, a2h, a3h, b0h, b1h);
                mma16(Oacc[nt], a0h, a1h, a2h, a3h, b0l, b1l);
                mma16(Oacc[nt], a0l, a1l, a2l, a3l, b0h, b1h);
            }
        }
    }

    // ---- epilogue ----
    float invA = 1.0f / lA, invB = 1.0f / lB;
    float* OA = O + ((size_t)n*LQ + l0 + rowA)*RS + h*DH;
    float* OB = O + ((size_t)n*LQ + l0 + rowB)*RS + h*DH;
    #pragma unroll
    for (int nt = 0; nt < 8; nt++) {
        *(float2*)(OA + nt*8 + 2*lr) = make_float2(Oacc[nt][0]*invA, Oacc[nt][1]*invA);
        *(float2*)(OB + nt*8 + 2*lr) = make_float2(Oacc[nt][2]*invB, Oacc[nt][3]*invB);
    }
}

extern "C" void kernel_launch(void* const* d_in, const int* in_sizes, int n_in,
                              void* d_out, int out_size)
{
    const float* Q   = (const float*)d_in[0];
    const float* K   = (const float*)d_in[1];
    const float* V   = (const float*)d_in[2];
    const int*   qm  = (const int*)d_in[3];
    const int*   kvm = (const int*)d_in[4];
    float*       O   = (float*)d_out;

    (void)in_sizes; (void)n_in; (void)out_size;

    cudaFuncSetAttribute(fullattn_bf16,
                         cudaFuncAttributeMaxDynamicSharedMemorySize, SMEM_BYTES);

    dim3 grid(LQ / BM, NH, NB);
    fullattn_bf16<<<grid, NTHR, SMEM_BYTES>>>(Q, K, V, qm, kvm, O);
}